// round 5
// baseline (speedup 1.0000x reference)
#include <cuda_runtime.h>
#include <cuda_bf16.h>
#include <math.h>

#define BB 32
#define HID 2048
#define INNER 4096
#define NH 8
#define HEAD 512
#define K3 12288
#define CAP 30.0f
#define EPS 1e-6f
#define GN_EPS 1e-5f
#define KSCALE 0.044194173824159216f   // 1/sqrt(512)

// ---------------- scratch (device globals; no allocs allowed) ----------------
__device__ float g_xn   [BB * HID];
__device__ float g_xg   [BB * INNER];
__device__ float g_xmc  [BB * INNER];
__device__ float g_qkv  [BB * K3];
__device__ float g_h    [BB * INNER];
__device__ float g_part [16 * BB * K3];            // split-K partials
__device__ float g_numer[BB * NH * 4 * HEAD];      // cell numer partials
__device__ float g_ig   [BB * NH];
__device__ float g_fg   [BB * NH];

// ---------------- output layout ----------------
#define Y_OFF    0
#define CONV_OFF 65536
#define CELL_OFF 458752
#define NORM_OFF 67567616
#define MAX_OFF  67698688

// ---------------- helpers ----------------
__device__ __forceinline__ void fma2(unsigned long long& d,
                                     unsigned long long a,
                                     unsigned long long b)
{
    asm("fma.rn.f32x2 %0, %1, %2, %0;" : "+l"(d) : "l"(a), "l"(b));
}
union U64F2 { unsigned long long u; float2 f; };

__device__ __forceinline__ void cp16(void* smem, const void* g)
{
    unsigned s = (unsigned)__cvta_generic_to_shared(smem);
    asm volatile("cp.async.cg.shared.global [%0], [%1], 16;\n" :: "r"(s), "l"(g));
}

// ============================================================================
// 1) RMSNorm
// ============================================================================
__global__ void rmsnorm_kernel(const float* __restrict__ x,
                               const float* __restrict__ rms_w)
{
    __shared__ float red[256];
    int b = blockIdx.x;
    int tid = threadIdx.x;
    const float* xr = x + b * HID;
    float s = 0.f;
    for (int i = tid; i < HID; i += 256) { float v = xr[i]; s += v * v; }
    red[tid] = s; __syncthreads();
    for (int st = 128; st > 0; st >>= 1) {
        if (tid < st) red[tid] += red[tid + st];
        __syncthreads();
    }
    float rstd = rsqrtf(red[0] / (float)HID + EPS);
    float* o = g_xn + b * HID;
    for (int i = tid; i < HID; i += 256) o[i] = xr[i] * rstd * rms_w[i];
}

// ============================================================================
// 2) GEMM: C[32,N] = A[32,K] @ W[N,K]^T, uneven split-K partials.
//    BM=32, BN=256, BK=16, 256 threads, thread tile 8m x 4n, fma2 k-dots.
//    W smem tile XOR-swizzled: chunk k4 of row r lives at column
//    (k4 ^ ((r>>3)&3))*4  -> conflict-free LDS.128 in the inner loop.
// ============================================================================
__global__ __launch_bounds__(256, 2) void gemm_v2(
    const float* __restrict__ A,
    const float* __restrict__ W1, float* __restrict__ C1,
    const float* __restrict__ W2, float* __restrict__ C2,
    int nb1, int N, int Kt)
{
    __shared__ __align__(16) float As[2][32][20];
    __shared__ __align__(16) float Ws[2][256][20];

    const int bx = blockIdx.x;
    const float* W = (bx < nb1) ? W1 : W2;
    float* C = ((bx < nb1) ? C1 : C2) + (size_t)blockIdx.y * 32 * N;
    const int n0 = ((bx < nb1) ? bx : bx - nb1) * 256;

    // uneven k-split over 16-wide tiles
    const int TT = Kt >> 4;
    const int G = gridDim.y;
    const int base = TT / G;
    const int rem = TT - base * G;
    const int by = blockIdx.y;
    const int tBeg = by * base + (by < rem ? by : rem);
    const int T = base + (by < rem ? 1 : 0);
    const int kBeg = tBeg << 4;

    const int t = threadIdx.x;
    const int tn = t & 63;
    const int tm = t >> 6;
    const int swz = (tn >> 3) & 3;       // load-side swizzle (row = j*64+tn)
    const int ssw = (t >> 3) & 3;        // store-side swizzle (row = t)

    const float* wsrc = W + (size_t)(n0 + t) * Kt + kBeg;
    const float* asrc = A + (size_t)(t >> 2) * Kt + kBeg + (t & 3) * 4;

    unsigned long long acc[8][4];
    #pragma unroll
    for (int i = 0; i < 8; i++)
        #pragma unroll
        for (int j = 0; j < 4; j++) acc[i][j] = 0ull;

    {
        #pragma unroll
        for (int k4 = 0; k4 < 4; k4++)
            cp16(&Ws[0][t][(k4 ^ ssw) * 4], wsrc + k4*4);
        if (t < 128)
            cp16(&As[0][t>>2][(t&3)*4], asrc);
        asm volatile("cp.async.commit_group;\n");
    }

    for (int tile = 0; tile < T; tile++) {
        const int cur = tile & 1;
        const int nxt = cur ^ 1;
        if (tile + 1 < T) {
            const float* ws = wsrc + (tile + 1) * 16;
            #pragma unroll
            for (int k4 = 0; k4 < 4; k4++)
                cp16(&Ws[nxt][t][(k4 ^ ssw) * 4], ws + k4*4);
            if (t < 128)
                cp16(&As[nxt][t>>2][(t&3)*4], asrc + (tile + 1) * 16);
            asm volatile("cp.async.commit_group;\n");
            asm volatile("cp.async.wait_group 1;\n");
        } else {
            asm volatile("cp.async.wait_group 0;\n");
        }
        __syncthreads();

        #pragma unroll
        for (int k4 = 0; k4 < 4; k4++) {
            ulonglong2 a[8];
            #pragma unroll
            for (int i = 0; i < 8; i++)
                a[i] = *(const ulonglong2*)&As[cur][tm*8 + i][k4*4];
            #pragma unroll
            for (int j = 0; j < 4; j++) {
                ulonglong2 w = *(const ulonglong2*)&Ws[cur][j*64 + tn][(k4 ^ swz) * 4];
                #pragma unroll
                for (int i = 0; i < 8; i++) {
                    fma2(acc[i][j], a[i].x, w.x);
                    fma2(acc[i][j], a[i].y, w.y);
                }
            }
        }
        __syncthreads();
    }

    #pragma unroll
    for (int i = 0; i < 8; i++) {
        float* cr = C + (size_t)(tm*8 + i) * N + n0;
        #pragma unroll
        for (int j = 0; j < 4; j++) {
            U64F2 u; u.u = acc[i][j];
            cr[j*64 + tn] = u.f.x + u.f.y;
        }
    }
}

// ============================================================================
// 3) Templated split-K reduce: C = sum_s part[s] (+ addv)
// ============================================================================
template<int S>
__global__ void reduce_split_t(const float* __restrict__ part, int elems,
                               const float* __restrict__ addv,
                               float* __restrict__ C)
{
    int i = blockIdx.x * blockDim.x + threadIdx.x;
    const float4* p = (const float4*)part;
    int q = elems >> 2;
    float4 s = p[i];
    #pragma unroll
    for (int j = 1; j < S; j++) {
        float4 t = p[i + (size_t)j * q];
        s.x += t.x; s.y += t.y; s.z += t.z; s.w += t.w;
    }
    if (addv) {
        float4 a = ((const float4*)addv)[i];
        s.x += a.x; s.y += a.y; s.z += a.z; s.w += a.w;
    }
    ((float4*)C)[i] = s;
}

// ============================================================================
// 4) Conv + fused xm split-reduce + silu + new_conv_state
// ============================================================================
__global__ void conv_kernel(const float* __restrict__ conv_state,
                            const float* __restrict__ conv_w,
                            const float* __restrict__ conv_b,
                            const float* __restrict__ xm_part,
                            float* __restrict__ out)
{
    int idx = blockIdx.x * blockDim.x + threadIdx.x;
    if (idx >= BB * INNER) return;
    int c = idx & (INNER - 1);
    float xm = 0.f;
    #pragma unroll
    for (int s = 0; s < 8; s++) xm += xm_part[(size_t)s * BB * INNER + idx];
    const float* cs = conv_state + (size_t)idx * 3;
    float s0 = cs[0], s1 = cs[1], s2 = cs[2];
    const float* w = conv_w + c * 4;
    float xc = s0*w[0] + s1*w[1] + s2*w[2] + xm*w[3] + conv_b[c];
    float* nc = out + CONV_OFF + (size_t)idx * 3;
    nc[0] = s1; nc[1] = s2; nc[2] = xm;
    g_xmc[idx] = xc / (1.f + expf(-xc));
}

// ============================================================================
// 5) Gates
// ============================================================================
__global__ __launch_bounds__(256) void gate_kernel(
    const float* __restrict__ Wi, const float* __restrict__ bi,
    const float* __restrict__ Wf, const float* __restrict__ bf,
    const float* __restrict__ max_state,
    float* __restrict__ out)
{
    __shared__ float ri[256], rf[256];
    int bh = blockIdx.x;
    int h = bh & (NH - 1);
    int b = bh >> 3;
    int tid = threadIdx.x;
    const float4* q4  = (const float4*)(g_qkv + (size_t)b * K3);
    const float4* wi4 = (const float4*)(Wi + (size_t)h * K3);
    const float4* wf4 = (const float4*)(Wf + (size_t)h * K3);
    float si = 0.f, sf = 0.f;
    #pragma unroll
    for (int r = 0; r < K3/4/256; r++) {
        int j = tid + r * 256;
        float4 q = q4[j], a = wi4[j], f = wf4[j];
        si += q.x*a.x + q.y*a.y + q.z*a.z + q.w*a.w;
        sf += q.x*f.x + q.y*f.y + q.z*f.z + q.w*f.w;
    }
    ri[tid] = si; rf[tid] = sf; __syncthreads();
    for (int st = 128; st > 0; st >>= 1) {
        if (tid < st) { ri[tid] += ri[tid+st]; rf[tid] += rf[tid+st]; }
        __syncthreads();
    }
    if (tid == 0) {
        float ig = CAP * tanhf((ri[0] + bi[h]) / CAP);
        float fg = CAP * tanhf((rf[0] + bf[h]) / CAP);
        float lf = (fg >= 0.f) ? -log1pf(expf(-fg)) : (fg - log1pf(expf(fg)));
        float m_old = max_state[bh];
        float m_new = fmaxf(ig, m_old + lf);
        g_ig[bh] = expf(ig - m_new);
        g_fg[bh] = expf(lf + m_old - m_new);
        out[MAX_OFF + bh] = m_new;
    }
}

// ============================================================================
// 6) Cell stream: grid = 4 chunks x 256 bh; 256 threads. Evict-streaming.
// ============================================================================
__global__ __launch_bounds__(256) void cell_stream(
    const float* __restrict__ cell_state,
    float* __restrict__ out)
{
    __shared__ float qsm[128], ksm[128];
    __shared__ float part[2][HEAD];

    const int bid = blockIdx.x;
    const int bh = bid >> 2;
    const int ch = bid & 3;
    const int h = bh & (NH - 1);
    const int b = bh >> 3;
    const int tid = threadIdx.x;

    const float* qrow = g_qkv + (size_t)b * K3 + h * HEAD;
    const float* krow = qrow + INNER;
    const float* vrow = qrow + 2 * INNER;
    const int d0 = ch * 128;

    if (tid < 128) {
        qsm[tid] = qrow[d0 + tid];
        ksm[tid] = krow[d0 + tid] * KSCALE;
    }
    __syncthreads();

    const float ig = g_ig[bh];
    const float fg = g_fg[bh];

    const int ct = tid & 127;
    const int rg = tid >> 7;
    const int e0 = ct * 4;
    float4 v = *(const float4*)(vrow + e0);
    float4 iv = make_float4(ig*v.x, ig*v.y, ig*v.z, ig*v.w);

    const float* cin  = cell_state + (size_t)bh * HEAD * HEAD;
    float*       cout = out + CELL_OFF + (size_t)bh * HEAD * HEAD;

    float4 nacc = make_float4(0.f, 0.f, 0.f, 0.f);
    #pragma unroll 8
    for (int dd = rg; dd < 128; dd += 2) {
        int d = d0 + dd;
        float4 cv = __ldcs((const float4*)(cin + (size_t)d * HEAD + e0));
        float kd = ksm[dd];
        float4 c;
        c.x = fmaf(fg, cv.x, kd * iv.x);
        c.y = fmaf(fg, cv.y, kd * iv.y);
        c.z = fmaf(fg, cv.z, kd * iv.z);
        c.w = fmaf(fg, cv.w, kd * iv.w);
        __stcs((float4*)(cout + (size_t)d * HEAD + e0), c);
        float qd = qsm[dd];
        nacc.x = fmaf(qd, c.x, nacc.x);
        nacc.y = fmaf(qd, c.y, nacc.y);
        nacc.z = fmaf(qd, c.z, nacc.z);
        nacc.w = fmaf(qd, c.w, nacc.w);
    }
    *(float4*)&part[rg][e0] = nacc;
    __syncthreads();
    if (tid < 128) {
        float4 p0 = *(const float4*)&part[0][e0];
        float4 p1 = *(const float4*)&part[1][e0];
        float4 s = make_float4(p0.x+p1.x, p0.y+p1.y, p0.z+p1.z, p0.w+p1.w);
        *(float4*)(g_numer + (size_t)bid * HEAD + e0) = s;
    }
}

// ============================================================================
// 7) Cell epilogue: norm_new + qn + denom + GroupNorm + gating -> h
// ============================================================================
__global__ __launch_bounds__(512) void cell_epi(
    const float* __restrict__ norm_state,
    const float* __restrict__ gn_w, const float* __restrict__ gn_b,
    const float* __restrict__ skip_w,
    float* __restrict__ out)
{
    __shared__ float red[512];
    const int bh = blockIdx.x;
    const int h = bh & (NH - 1);
    const int b = bh >> 3;
    const int tid = threadIdx.x;

    const float* qrow = g_qkv + (size_t)b * K3 + h * HEAD;
    const float* krow = qrow + INNER;
    float q = qrow[tid];
    float k = krow[tid] * KSCALE;

    const float ig = g_ig[bh];
    const float fg = g_fg[bh];
    const float m_new = out[MAX_OFF + bh];

    float num = g_numer[(size_t)(bh*4+0) * HEAD + tid]
              + g_numer[(size_t)(bh*4+1) * HEAD + tid]
              + g_numer[(size_t)(bh*4+2) * HEAD + tid]
              + g_numer[(size_t)(bh*4+3) * HEAD + tid];

    float nn = fmaf(fg, norm_state[(size_t)bh * HEAD + tid], ig * k);
    out[NORM_OFF + (size_t)bh * HEAD + tid] = nn;

    red[tid] = q * nn; __syncthreads();
    for (int st = 256; st > 0; st >>= 1) {
        if (tid < st) red[tid] += red[tid+st];
        __syncthreads();
    }
    float qn = red[0]; __syncthreads();
    float denom = fmaxf(fabsf(qn), expf(-m_new)) + EPS;
    float o = num / denom;

    red[tid] = o; __syncthreads();
    for (int st = 256; st > 0; st >>= 1) {
        if (tid < st) red[tid] += red[tid+st];
        __syncthreads();
    }
    float mu = red[0] / (float)HEAD; __syncthreads();
    float dv = o - mu;
    red[tid] = dv * dv; __syncthreads();
    for (int st = 256; st > 0; st >>= 1) {
        if (tid < st) red[tid] += red[tid+st];
        __syncthreads();
    }
    float rstd = rsqrtf(red[0] / (float)HEAD + GN_EPS);

    int c = h * HEAD + tid;
    size_t gidx = (size_t)b * INNER + c;
    float og = fmaf(dv * rstd, gn_w[c], gn_b[c]);
    float xg = g_xg[gidx];
    float sg = xg / (1.f + expf(-xg));
    g_h[gidx] = (og + skip_w[c] * g_xmc[gidx]) * sg;
}

// ============================================================================
extern "C" void kernel_launch(void* const* d_in, const int* in_sizes, int n_in,
                              void* d_out, int out_size)
{
    const float* x          = (const float*)d_in[0];
    const float* conv_state = (const float*)d_in[1];
    const float* cell_state = (const float*)d_in[2];
    const float* norm_state = (const float*)d_in[3];
    const float* max_state  = (const float*)d_in[4];
    const float* rms_w      = (const float*)d_in[5];
    const float* Wx         = (const float*)d_in[6];
    const float* Wg         = (const float*)d_in[7];
    const float* Wqkv       = (const float*)d_in[8];
    const float* conv_w     = (const float*)d_in[9];
    const float* conv_b     = (const float*)d_in[10];
    const float* Wi         = (const float*)d_in[11];
    const float* bi         = (const float*)d_in[12];
    const float* Wf         = (const float*)d_in[13];
    const float* bf         = (const float*)d_in[14];
    const float* gn_w       = (const float*)d_in[15];
    const float* gn_b       = (const float*)d_in[16];
    const float* Wdown      = (const float*)d_in[17];
    const float* skip_w     = (const float*)d_in[18];
    float* out = (float*)d_out;

    float* pxn;   cudaGetSymbolAddress((void**)&pxn,   g_xn);
    float* pxg;   cudaGetSymbolAddress((void**)&pxg,   g_xg);
    float* pxmc;  cudaGetSymbolAddress((void**)&pxmc,  g_xmc);
    float* pqkv;  cudaGetSymbolAddress((void**)&pqkv,  g_qkv);
    float* ph;    cudaGetSymbolAddress((void**)&ph,    g_h);
    float* ppart; cudaGetSymbolAddress((void**)&ppart, g_part);

    float* pp2 = ppart + (size_t)8 * BB * INNER;   // Wg partial base

    // 1) rmsnorm
    rmsnorm_kernel<<<BB, 256>>>(x, rms_w);

    // 2) x_mlstm & x_gate fused, split-K 8: grid (16+16, 8) = 256 blocks
    gemm_v2<<<dim3(32, 8), 256>>>(pxn, Wx, ppart, Wg, pp2, 16, INNER, HID);
    reduce_split_t<8><<<(BB*INNER/4)/256, 256>>>(pp2, BB*INNER, nullptr, pxg);

    // 3) conv + fused xm reduce + silu + new_conv_state
    conv_kernel<<<(BB*INNER)/256, 256>>>(conv_state, conv_w, conv_b, ppart, out);

    // 4) qkv = xmc @ Wqkv^T, uneven split-K 6: grid (48, 6) = 288 blocks
    gemm_v2<<<dim3(48, 6), 256>>>(pxmc, Wqkv, ppart, nullptr, nullptr,
                                  48, K3, INNER);
    reduce_split_t<6><<<(BB*K3/4)/256, 256>>>(ppart, BB*K3, nullptr, pqkv);

    // 5) gates
    gate_kernel<<<BB*NH, 256>>>(Wi, bi, Wf, bf, max_state, out);

    // 6) cell stream: 1024 blocks, one wave
    cell_stream<<<BB*NH*4, 256>>>(cell_state, out);

    // 7) cell epilogue -> h
    cell_epi<<<BB*NH, 512>>>(norm_state, gn_w, gn_b, skip_w, out);

    // 8) y = h @ Wdown^T + x, split-K 32: grid (8, 32) = 256 blocks
    gemm_v2<<<dim3(8, 32), 256>>>(ph, Wdown, ppart, nullptr, nullptr,
                                  8, HID, INNER);
    reduce_split_t<32><<<(BB*HID/4)/256, 256>>>(ppart, BB*HID, x, out + Y_OFF);
}